// round 15
// baseline (speedup 1.0000x reference)
#include <cuda_runtime.h>
#include <cuda_fp16.h>
#include <cstdint>

#define NN   50000
#define EE   800000
#define DIN  64
#define DH   128
#define DOUT 64

#define WS_H 136     // Ws stride in halves ([n][k] transposed weights)
#define AS_H 136     // As stride in halves

// ---------------- scratch (static device globals; no allocation) ----------------
// NOTE: g_cnt is zero at module load and re-zeroed by k_scatter each run (invariant).
__device__ int    g_is64;
__device__ int    g_cnt[NN];
__device__ int    g_offs[NN + 1];
__device__ int    g_cursor[NN];
__device__ int    g_bsum[64];
__device__ int    g_src[EE];
__device__ __half g_xh[(size_t)NN * DIN];      // x fp16 (gather payload + GEMM1 A)
__device__ __half g_agg1h[(size_t)NN * DIN];   // segsum(x[src]) fp16 (GEMM1 A)
__device__ __half g_h[(size_t)NN * DH];        // layer-1 output fp16 (GEMM2 A)
__device__ __half g_yh[(size_t)NN * DOUT];     // y = h@W2l fp16 (gather payload)
__device__ float  g_z[(size_t)NN * DOUT];      // z = h@W2r + b2 fp32

// ---------------- edge index helper (int32 vs int64) ------------------------------
__device__ __forceinline__ int edge_val(const void* ei, int idx) {
    if (g_is64) return (int)((const long long*)ei)[idx];
    return ((const int*)ei)[idx];
}

// fused: x->fp16 convert + per-CTA dtype detect + edge histogram.
// Grid: EE = NN*DIN/4 = 800000 threads. Requires g_cnt == 0 on entry (see note above).
__global__ void k_init(const float* __restrict__ x, const void* __restrict__ ei) {
    __shared__ int s_is64;
    const int* ei32 = (const int*)ei;
    if (threadIdx.x == 0) s_is64 = 1;
    __syncthreads();
    // int64 little-endian values < 2^31 -> every odd 32-bit word is zero.
    if (threadIdx.x < 128 && ei32[2 * threadIdx.x + 1] != 0) s_is64 = 0;  // benign race
    __syncthreads();

    int i = blockIdx.x * blockDim.x + threadIdx.x;
    if (i < (NN * DIN) / 4) {
        float4 v = *reinterpret_cast<const float4*>(x + 4 * i);
        __half2 h0 = __floats2half2_rn(v.x, v.y);
        __half2 h1 = __floats2half2_rn(v.z, v.w);
        uint2 pack;
        pack.x = *reinterpret_cast<uint32_t*>(&h0);
        pack.y = *reinterpret_cast<uint32_t*>(&h1);
        *reinterpret_cast<uint2*>(g_xh + 4 * i) = pack;
    }
    if (i < EE) {
        int d = s_is64 ? (int)((const long long*)ei)[EE + i] : ei32[EE + i];
        atomicAdd(&g_cnt[d], 1);
    }
    if (i == 0) g_is64 = s_is64;   // for later kernels
}

// ---------------- CSR scan (per-block inclusive + redundant block-sum prefix) -----
__global__ void k_scan1() {
    __shared__ int s[1024];
    int t = threadIdx.x;
    int gid = blockIdx.x * 1024 + t;
    int v = (gid < NN) ? g_cnt[gid] : 0;
    s[t] = v;
    __syncthreads();
    for (int o = 1; o < 1024; o <<= 1) {
        int x = (t >= o) ? s[t - o] : 0;
        __syncthreads();
        s[t] += x;
        __syncthreads();
    }
    if (gid < NN) g_offs[gid + 1] = s[t];
    if (t == 1023) g_bsum[blockIdx.x] = s[1023];
}

// merged scan2+scan3: each block computes its own block-sum prefix (<=49 serial adds)
__global__ void k_scan3() {
    __shared__ int boff;
    int t = threadIdx.x;
    if (t == 0) {
        int sum = 0;
        for (int i = 0; i < (int)blockIdx.x; i++) sum += g_bsum[i];
        boff = sum;
    }
    __syncthreads();
    int gid = blockIdx.x * 1024 + t;
    if (gid < NN) {
        int f = g_offs[gid + 1] + boff;
        g_offs[gid + 1] = f;
        g_cursor[gid] = f - g_cnt[gid];
        if (gid == 0) g_offs[0] = 0;
    }
}

// scatter, 4 edges/thread with batched loads (4 independent atomic chains in flight),
// + re-zero counters for the next run (keeps the g_cnt==0 invariant)
__global__ void k_scatter(const void* __restrict__ ei) {
    int tidg = blockIdx.x * blockDim.x + threadIdx.x;
    int base = tidg * 4;
    if (base + 4 <= EE) {
        int s0, s1, s2, s3, d0, d1, d2, d3;
        if (g_is64) {
            const longlong2* p = (const longlong2*)ei;
            longlong2 sa = __ldg(&p[base / 2]),        sb = __ldg(&p[base / 2 + 1]);
            longlong2 da = __ldg(&p[(EE + base) / 2]), db = __ldg(&p[(EE + base) / 2 + 1]);
            s0 = (int)sa.x; s1 = (int)sa.y; s2 = (int)sb.x; s3 = (int)sb.y;
            d0 = (int)da.x; d1 = (int)da.y; d2 = (int)db.x; d3 = (int)db.y;
        } else {
            const int4* p = (const int4*)ei;
            int4 sv = __ldg(&p[base / 4]);
            int4 dv = __ldg(&p[(EE + base) / 4]);
            s0 = sv.x; s1 = sv.y; s2 = sv.z; s3 = sv.w;
            d0 = dv.x; d1 = dv.y; d2 = dv.z; d3 = dv.w;
        }
        int p0 = atomicAdd(&g_cursor[d0], 1);
        int p1 = atomicAdd(&g_cursor[d1], 1);
        int p2 = atomicAdd(&g_cursor[d2], 1);
        int p3 = atomicAdd(&g_cursor[d3], 1);
        g_src[p0] = s0;
        g_src[p1] = s1;
        g_src[p2] = s2;
        g_src[p3] = s3;
    } else {
        for (int e = base; e < EE; e++) {
            int s = edge_val(ei, e);
            int d = edge_val(ei, EE + e);
            int pos = atomicAdd(&g_cursor[d], 1);
            g_src[pos] = s;
        }
    }
    if (tidg < NN) g_cnt[tidg] = 0;
}

// ---------------- fp16 gather-sum of one node row (warp-collective) ---------------
__device__ __forceinline__ float2 gather_row_h(const __half* __restrict__ feat,
                                               int node, int lane) {
    int s = g_offs[node], e = g_offs[node + 1];
    float2 a0 = make_float2(0.f, 0.f), a1 = make_float2(0.f, 0.f);
    float2 a2 = make_float2(0.f, 0.f), a3 = make_float2(0.f, 0.f);
    int i = s;
    for (; i + 4 <= e; i += 4) {
        int s0 = __ldg(&g_src[i]),     s1 = __ldg(&g_src[i + 1]);
        int s2 = __ldg(&g_src[i + 2]), s3 = __ldg(&g_src[i + 3]);
        float2 v0 = __half22float2(*reinterpret_cast<const __half2*>(feat + (size_t)s0 * 64 + 2 * lane));
        float2 v1 = __half22float2(*reinterpret_cast<const __half2*>(feat + (size_t)s1 * 64 + 2 * lane));
        float2 v2 = __half22float2(*reinterpret_cast<const __half2*>(feat + (size_t)s2 * 64 + 2 * lane));
        float2 v3 = __half22float2(*reinterpret_cast<const __half2*>(feat + (size_t)s3 * 64 + 2 * lane));
        a0.x += v0.x; a0.y += v0.y;  a1.x += v1.x; a1.y += v1.y;
        a2.x += v2.x; a2.y += v2.y;  a3.x += v3.x; a3.y += v3.y;
    }
    for (; i < e; i++) {
        int sr = __ldg(&g_src[i]);
        float2 v = __half22float2(*reinterpret_cast<const __half2*>(feat + (size_t)sr * 64 + 2 * lane));
        a0.x += v.x; a0.y += v.y;
    }
    return make_float2((a0.x + a1.x) + (a2.x + a3.x),
                       (a0.y + a1.y) + (a2.y + a3.y));
}

// ---------------- layer-1 aggregation: agg1h = segsum(xh[src]) fp16 ---------------
__global__ void k_agg1() {
    int w = (blockIdx.x * blockDim.x + threadIdx.x) >> 5;
    if (w >= NN) return;
    int lane = threadIdx.x & 31;
    float2 acc = gather_row_h(g_xh, w, lane);
    __half2 hp = __floats2half2_rn(acc.x, acc.y);
    *reinterpret_cast<uint32_t*>(g_agg1h + (size_t)w * 64 + 2 * lane) =
        *reinterpret_cast<uint32_t*>(&hp);
}

// ---------------- fp16 mma m16n8k16 ----------------
__device__ __forceinline__ void mma_f16(float4& d, const uint32_t* a, const uint32_t* b) {
    asm volatile("mma.sync.aligned.m16n8k16.row.col.f32.f16.f16.f32 "
        "{%0,%1,%2,%3}, {%4,%5,%6,%7}, {%8,%9}, {%0,%1,%2,%3};"
        : "+f"(d.x), "+f"(d.y), "+f"(d.z), "+f"(d.w)
        : "r"(a[0]), "r"(a[1]), "r"(a[2]), "r"(a[3]), "r"(b[0]), "r"(b[1]));
}

// ---------------- layer 1: fp16 GEMM + register epilogue (norm/BN/ReLU) -----------
// h = relu(bn(l2norm([agg1h|xh] @ [W1l;W1r] + b1))), h stored fp16.
__global__ __launch_bounds__(256, 3)
void k_tgemm1(const float* __restrict__ Wl, const float* __restrict__ Wr,
              const float* __restrict__ bias,
              const float* __restrict__ gam, const float* __restrict__ bet,
              const float* __restrict__ rm,  const float* __restrict__ rv) {
    constexpr int BM = 64, K = 128, NOUT = 128;
    extern __shared__ __half smh[];
    __half* Ws16 = smh;                          // [NOUT][WS_H]
    __half* As16 = smh + NOUT * WS_H;            // [BM][AS_H]
    float*  ssqp = reinterpret_cast<float*>(smh + NOUT * WS_H + BM * AS_H);  // [4][64]

    const int tid  = threadIdx.x;
    const int lane = tid & 31, wid = tid >> 5;
    const int g = lane >> 2, t = lane & 3;
    const int wm = wid >> 2, wn = wid & 3;

    // stage W transposed: Ws16[n][k] = W[k][n]
    for (int v = tid; v < (K * NOUT) / 4; v += 256) {
        int n = v & 127, k0 = (v >> 7) * 4;
        float w0, w1, w2, w3;
        if (k0 < 64) {
            w0 = Wl[k0 * NOUT + n];       w1 = Wl[(k0 + 1) * NOUT + n];
            w2 = Wl[(k0 + 2) * NOUT + n]; w3 = Wl[(k0 + 3) * NOUT + n];
        } else {
            int kk = k0 - 64;
            w0 = Wr[kk * NOUT + n];       w1 = Wr[(kk + 1) * NOUT + n];
            w2 = Wr[(kk + 2) * NOUT + n]; w3 = Wr[(kk + 3) * NOUT + n];
        }
        __half2 p0 = __floats2half2_rn(w0, w1), p1 = __floats2half2_rn(w2, w3);
        uint2 pk;
        pk.x = *reinterpret_cast<uint32_t*>(&p0);
        pk.y = *reinterpret_cast<uint32_t*>(&p1);
        *reinterpret_cast<uint2*>(Ws16 + n * WS_H + k0) = pk;
    }

    // per-lane column params for this warp's columns c = wn*32 + j*8 + 2t
    float2 bb[4], Am[4], Cm[4];
#pragma unroll
    for (int j = 0; j < 4; j++) {
        int c = wn * 32 + j * 8 + 2 * t;
        bb[j] = *reinterpret_cast<const float2*>(bias + c);
        float2 Gv = *reinterpret_cast<const float2*>(gam + c);
        float2 Rv = *reinterpret_cast<const float2*>(rv  + c);
        float2 Mv = *reinterpret_cast<const float2*>(rm  + c);
        float2 Bv = *reinterpret_cast<const float2*>(bet + c);
        float isx = rsqrtf(Rv.x + 1e-5f), isy = rsqrtf(Rv.y + 1e-5f);
        Am[j] = make_float2(Gv.x * isx, Gv.y * isy);
        Cm[j] = make_float2(Bv.x - Am[j].x * Mv.x, Bv.y - Am[j].y * Mv.y);
    }

    const int numTiles = (NN + BM - 1) / BM;
    for (int tile = blockIdx.x; tile < numTiles; tile += gridDim.x) {
        __syncthreads();   // As16 + ssqp reads of previous tile done
        const int base = tile * BM;

        for (int v = tid; v < (BM * K) / 4; v += 256) {
            int idx = v * 4, r = idx >> 7, c = idx & 127;
            int node = base + r;
            uint2 pk = make_uint2(0u, 0u);
            if (node < NN) {
                if (c < 64) pk = *reinterpret_cast<const uint2*>(g_agg1h + (size_t)node * 64 + c);
                else        pk = *reinterpret_cast<const uint2*>(g_xh + (size_t)node * 64 + (c - 64));
            }
            *reinterpret_cast<uint2*>(As16 + r * AS_H + c) = pk;
        }
        __syncthreads();

        float4 acc[2][4];
#pragma unroll
        for (int i = 0; i < 2; i++)
#pragma unroll
            for (int j = 0; j < 4; j++) acc[i][j] = make_float4(0.f, 0.f, 0.f, 0.f);

#pragma unroll
        for (int kk = 0; kk < 8; kk++) {
            const int cb = kk * 16;
            uint32_t a[2][4], b[4][2];
#pragma unroll
            for (int i = 0; i < 2; i++) {
                int r0 = wm * 32 + i * 16 + g;
                const __half* p = As16 + r0 * AS_H + cb + 2 * t;
                a[i][0] = *reinterpret_cast<const uint32_t*>(p);
                a[i][1] = *reinterpret_cast<const uint32_t*>(p + 8 * AS_H);
                a[i][2] = *reinterpret_cast<const uint32_t*>(p + 8);
                a[i][3] = *reinterpret_cast<const uint32_t*>(p + 8 * AS_H + 8);
            }
#pragma unroll
            for (int j = 0; j < 4; j++) {
                int n = wn * 32 + j * 8 + g;
                const __half* p = Ws16 + n * WS_H + cb + 2 * t;
                b[j][0] = *reinterpret_cast<const uint32_t*>(p);
                b[j][1] = *reinterpret_cast<const uint32_t*>(p + 8);
            }
#pragma unroll
            for (int i = 0; i < 2; i++)
#pragma unroll
                for (int j = 0; j < 4; j++) mma_f16(acc[i][j], a[i], b[j]);
        }

        // bias + per-row partial sum of squares, quad-reduce over t
        float p0[2], p1[2];
#pragma unroll
        for (int i = 0; i < 2; i++) {
            p0[i] = 0.f; p1[i] = 0.f;
#pragma unroll
            for (int j = 0; j < 4; j++) {
                acc[i][j].x += bb[j].x; acc[i][j].y += bb[j].y;
                acc[i][j].z += bb[j].x; acc[i][j].w += bb[j].y;
                p0[i] += acc[i][j].x * acc[i][j].x + acc[i][j].y * acc[i][j].y;
                p1[i] += acc[i][j].z * acc[i][j].z + acc[i][j].w * acc[i][j].w;
            }
            p0[i] += __shfl_xor_sync(0xffffffffu, p0[i], 1);
            p0[i] += __shfl_xor_sync(0xffffffffu, p0[i], 2);
            p1[i] += __shfl_xor_sync(0xffffffffu, p1[i], 1);
            p1[i] += __shfl_xor_sync(0xffffffffu, p1[i], 2);
        }
        if (t == 0) {
#pragma unroll
            for (int i = 0; i < 2; i++) {
                int r = wm * 32 + i * 16 + g;
                ssqp[wn * 64 + r]     = p0[i];
                ssqp[wn * 64 + r + 8] = p1[i];
            }
        }
        __syncthreads();

        // total ssq, normalize, BN(+ReLU), store fp16 h from registers
#pragma unroll
        for (int i = 0; i < 2; i++) {
            int r = wm * 32 + i * 16 + g;
            float ss0 = ssqp[r] + ssqp[64 + r] + ssqp[128 + r] + ssqp[192 + r];
            float ss1 = ssqp[r + 8] + ssqp[64 + r + 8] + ssqp[128 + r + 8] + ssqp[192 + r + 8];
            float sc0 = 1.0f / fmaxf(sqrtf(ss0), 1e-12f);
            float sc1 = 1.0f / fmaxf(sqrtf(ss1), 1e-12f);
            int n0 = base + r, n1 = n0 + 8;
#pragma unroll
            for (int j = 0; j < 4; j++) {
                int c = wn * 32 + j * 8 + 2 * t;
                if (n0 < NN) {
                    float ox = fmaxf(Am[j].x * (acc[i][j].x * sc0) + Cm[j].x, 0.f);
                    float oy = fmaxf(Am[j].y * (acc[i][j].y * sc0) + Cm[j].y, 0.f);
                    __half2 hp = __floats2half2_rn(ox, oy);
                    *reinterpret_cast<uint32_t*>(g_h + (size_t)n0 * NOUT + c) =
                        *reinterpret_cast<uint32_t*>(&hp);
                }
                if (n1 < NN) {
                    float oz = fmaxf(Am[j].x * (acc[i][j].z * sc1) + Cm[j].x, 0.f);
                    float ow = fmaxf(Am[j].y * (acc[i][j].w * sc1) + Cm[j].y, 0.f);
                    __half2 hp = __floats2half2_rn(oz, ow);
                    *reinterpret_cast<uint32_t*>(g_h + (size_t)n1 * NOUT + c) =
                        *reinterpret_cast<uint32_t*>(&hp);
                }
            }
        }
    }
}

// ---------------- layer 2 projection: y(fp16)=h@W2l ; z(fp32)=h@W2r+b2 ------------
__global__ __launch_bounds__(256)
void k_tgemm2(const float* __restrict__ Wl, const float* __restrict__ Wr,
              const float* __restrict__ bias) {
    constexpr int BM = 64, K = 128, NOUT = 128;
    extern __shared__ __half smh[];
    __half* Ws16 = smh;                    // [NOUT][WS_H]
    __half* As16 = smh + NOUT * WS_H;      // [BM][AS_H]

    const int tid  = threadIdx.x;
    const int lane = tid & 31, wid = tid >> 5;
    const int g = lane >> 2, t = lane & 3;
    const int wm = wid >> 2, wn = wid & 3;

    for (int v = tid; v < (K * NOUT) / 4; v += 256) {
        int n = v & 127, k0 = (v >> 7) * 4;
        float w0, w1, w2, w3;
        if (n < 64) {
            w0 = Wl[k0 * 64 + n];       w1 = Wl[(k0 + 1) * 64 + n];
            w2 = Wl[(k0 + 2) * 64 + n]; w3 = Wl[(k0 + 3) * 64 + n];
        } else {
            int nn = n - 64;
            w0 = Wr[k0 * 64 + nn];       w1 = Wr[(k0 + 1) * 64 + nn];
            w2 = Wr[(k0 + 2) * 64 + nn]; w3 = Wr[(k0 + 3) * 64 + nn];
        }
        __half2 p0 = __floats2half2_rn(w0, w1), p1 = __floats2half2_rn(w2, w3);
        uint2 pk;
        pk.x = *reinterpret_cast<uint32_t*>(&p0);
        pk.y = *reinterpret_cast<uint32_t*>(&p1);
        *reinterpret_cast<uint2*>(Ws16 + n * WS_H + k0) = pk;
    }

    float2 bz[4];
#pragma unroll
    for (int j = 0; j < 4; j++) {
        int c = wn * 32 + j * 8 + 2 * t;
        if (c >= 64) bz[j] = *reinterpret_cast<const float2*>(bias + (c - 64));
        else         bz[j] = make_float2(0.f, 0.f);
    }

    const int numTiles = (NN + BM - 1) / BM;
    for (int tile = blockIdx.x; tile < numTiles; tile += gridDim.x) {
        __syncthreads();
        const int base = tile * BM;

        for (int v = tid; v < (BM * K) / 4; v += 256) {
            int idx = v * 4, r = idx >> 7, c = idx & 127;
            int node = base + r;
            uint2 pk = make_uint2(0u, 0u);
            if (node < NN)
                pk = *reinterpret_cast<const uint2*>(g_h + (size_t)node * 128 + c);
            *reinterpret_cast<uint2*>(As16 + r * AS_H + c) = pk;
        }
        __syncthreads();

        float4 acc[2][4];
#pragma unroll
        for (int i = 0; i < 2; i++)
#pragma unroll
            for (int j = 0; j < 4; j++) acc[i][j] = make_float4(0.f, 0.f, 0.f, 0.f);

#pragma unroll
        for (int kk = 0; kk < 8; kk++) {
            const int cb = kk * 16;
            uint32_t a[2][4], b[4][2];
#pragma unroll
            for (int i = 0; i < 2; i++) {
                int r0 = wm * 32 + i * 16 + g;
                const __half* p = As16 + r0 * AS_H + cb + 2 * t;
                a[i][0] = *reinterpret_cast<const uint32_t*>(p);
                a[i][1] = *reinterpret_cast<const uint32_t*>(p + 8 * AS_H);
                a[i][2] = *reinterpret_cast<const uint32_t*>(p + 8);
                a[i][3] = *reinterpret_cast<const uint32_t*>(p + 8 * AS_H + 8);
            }
#pragma unroll
            for (int j = 0; j < 4; j++) {
                int n = wn * 32 + j * 8 + g;
                const __half* p = Ws16 + n * WS_H + cb + 2 * t;
                b[j][0] = *reinterpret_cast<const uint32_t*>(p);
                b[j][1] = *reinterpret_cast<const uint32_t*>(p + 8);
            }
#pragma unroll
            for (int i = 0; i < 2; i++)
#pragma unroll
                for (int j = 0; j < 4; j++) mma_f16(acc[i][j], a[i], b[j]);
        }

#pragma unroll
        for (int i = 0; i < 2; i++) {
            int r0 = base + wm * 32 + i * 16 + g;
            int r1 = r0 + 8;
#pragma unroll
            for (int j = 0; j < 4; j++) {
                int c = wn * 32 + j * 8 + 2 * t;
                float4 v = acc[i][j];
                if (c < 64) {
                    if (r0 < NN) {
                        __half2 hp = __floats2half2_rn(v.x, v.y);
                        *reinterpret_cast<uint32_t*>(g_yh + (size_t)r0 * 64 + c) =
                            *reinterpret_cast<uint32_t*>(&hp);
                    }
                    if (r1 < NN) {
                        __half2 hp = __floats2half2_rn(v.z, v.w);
                        *reinterpret_cast<uint32_t*>(g_yh + (size_t)r1 * 64 + c) =
                            *reinterpret_cast<uint32_t*>(&hp);
                    }
                } else {
                    int cz = c - 64;
                    if (r0 < NN)
                        *reinterpret_cast<float2*>(g_z + (size_t)r0 * 64 + cz) =
                            make_float2(v.x + bz[j].x, v.y + bz[j].y);
                    if (r1 < NN)
                        *reinterpret_cast<float2*>(g_z + (size_t)r1 * 64 + cz) =
                            make_float2(v.z + bz[j].x, v.w + bz[j].y);
                }
            }
        }
    }
}

// ---------------- layer-2 final: gather y(fp16), add z, L2norm, BN -> out ---------
__global__ void k_final(const float* __restrict__ gam, const float* __restrict__ bet,
                        const float* __restrict__ rm,  const float* __restrict__ rv,
                        float* __restrict__ out) {
    int w = (blockIdx.x * blockDim.x + threadIdx.x) >> 5;
    if (w >= NN) return;
    int lane = threadIdx.x & 31;

    float2 v = gather_row_h(g_yh, w, lane);
    float2 z = *reinterpret_cast<const float2*>(g_z + (size_t)w * 64 + 2 * lane);
    v.x += z.x; v.y += z.y;

    float ss = v.x * v.x + v.y * v.y;
#pragma unroll
    for (int o = 16; o > 0; o >>= 1) ss += __shfl_xor_sync(0xffffffffu, ss, o);
    float scale = 1.0f / fmaxf(sqrtf(ss), 1e-12f);

    float2 G  = *reinterpret_cast<const float2*>(gam + 2 * lane);
    float2 B  = *reinterpret_cast<const float2*>(bet + 2 * lane);
    float2 RM = *reinterpret_cast<const float2*>(rm  + 2 * lane);
    float2 RV = *reinterpret_cast<const float2*>(rv  + 2 * lane);
    float2 o;
    o.x = G.x * (v.x * scale - RM.x) * rsqrtf(RV.x + 1e-5f) + B.x;
    o.y = G.y * (v.y * scale - RM.y) * rsqrtf(RV.y + 1e-5f) + B.y;
    *reinterpret_cast<float2*>(out + (size_t)w * 64 + 2 * lane) = o;
}

// ---------------- launch ----------------
extern "C" void kernel_launch(void* const* d_in, const int* in_sizes, int n_in,
                              void* d_out, int out_size) {
    const float* x    = (const float*)d_in[0];
    const void*  ei   = d_in[1];
    const float* W1l  = (const float*)d_in[2];
    const float* b1   = (const float*)d_in[3];
    const float* W1r  = (const float*)d_in[4];
    const float* gam1 = (const float*)d_in[5];
    const float* bet1 = (const float*)d_in[6];
    const float* rm1  = (const float*)d_in[7];
    const float* rv1  = (const float*)d_in[8];
    const float* W2l  = (const float*)d_in[9];
    const float* b2   = (const float*)d_in[10];
    const float* W2r  = (const float*)d_in[11];
    const float* gam2 = (const float*)d_in[12];
    const float* bet2 = (const float*)d_in[13];
    const float* rm2  = (const float*)d_in[14];
    const float* rv2  = (const float*)d_in[15];
    float* out = (float*)d_out;

    constexpr int SMEM1 = (128 * WS_H + 64 * AS_H) * 2 + 4 * 64 * 4;  // 53,248 B
    constexpr int SMEM2 = (128 * WS_H + 64 * AS_H) * 2;               // 52,224 B
    cudaFuncSetAttribute(k_tgemm1, cudaFuncAttributeMaxDynamicSharedMemorySize, SMEM1);
    cudaFuncSetAttribute(k_tgemm2, cudaFuncAttributeMaxDynamicSharedMemorySize, SMEM2);

    const int NB = (NN + 1023) / 1024;
    const int EB = (EE + 255) / 256;
    const int SB = (EE / 4 + 255) / 256;    // scatter: 4 edges per thread
    const int WARP_BLOCKS = (NN * 32 + 255) / 256;

    // fused front-end: (convert + detect + hist) -> scan1 -> (scan2+scan3) -> (scatter x4 + re-zero)
    k_init<<<EB, 256>>>(x, ei);
    k_scan1<<<NB, 1024>>>();
    k_scan3<<<NB, 1024>>>();
    k_scatter<<<SB, 256>>>(ei);

    // layer 1: fp16 gather -> fp16 tensor GEMM + register epilogue (h fp16)
    k_agg1<<<WARP_BLOCKS, 256>>>();
    k_tgemm1<<<444, 256, SMEM1>>>(W1l, W1r, b1, gam1, bet1, rm1, rv1);

    // layer 2: fp16 projection GEMM (y fp16, z fp32, direct epilogue) -> final
    k_tgemm2<<<592, 256, SMEM2>>>(W2l, W2r, b2);
    k_final<<<WARP_BLOCKS, 256>>>(gam2, bet2, rm2, rv2, out);
}

// round 16
// speedup vs baseline: 1.0159x; 1.0159x over previous
#include <cuda_runtime.h>
#include <cuda_fp16.h>
#include <cstdint>

#define NN   50000
#define EE   800000
#define DIN  64
#define DH   128
#define DOUT 64

#define WS_H 136     // Ws stride in halves ([n][k] transposed weights)
#define AS_H 136     // As stride in halves

// ---------------- scratch (static device globals; no allocation) ----------------
// NOTE: g_cnt is zero at module load and re-zeroed by k_scatter each run (invariant).
__device__ int    g_is64;
__device__ int    g_cnt[NN];
__device__ int    g_offs[NN + 1];
__device__ int    g_cursor[NN];
__device__ int    g_src[EE];
__device__ __half g_xh[(size_t)NN * DIN];      // x fp16 (gather payload + GEMM1 A)
__device__ __half g_agg1h[(size_t)NN * DIN];   // segsum(x[src]) fp16 (GEMM1 A)
__device__ __half g_h[(size_t)NN * DH];        // layer-1 output fp16 (GEMM2 A)
__device__ __half g_yh[(size_t)NN * DOUT];     // y = h@W2l fp16 (gather payload)
__device__ float  g_z[(size_t)NN * DOUT];      // z = h@W2r + b2 fp32

// ---------------- edge index helper (int32 vs int64) ------------------------------
__device__ __forceinline__ int edge_val(const void* ei, int idx) {
    if (g_is64) return (int)((const long long*)ei)[idx];
    return ((const int*)ei)[idx];
}

// fused: x->fp16 convert + per-CTA dtype detect + edge histogram.
// Grid: EE = NN*DIN/4 = 800000 threads. Requires g_cnt == 0 on entry (see note above).
__global__ void k_init(const float* __restrict__ x, const void* __restrict__ ei) {
    __shared__ int s_is64;
    const int* ei32 = (const int*)ei;
    if (threadIdx.x == 0) s_is64 = 1;
    __syncthreads();
    // int64 little-endian values < 2^31 -> every odd 32-bit word is zero.
    if (threadIdx.x < 128 && ei32[2 * threadIdx.x + 1] != 0) s_is64 = 0;  // benign race
    __syncthreads();

    int i = blockIdx.x * blockDim.x + threadIdx.x;
    if (i < (NN * DIN) / 4) {
        float4 v = *reinterpret_cast<const float4*>(x + 4 * i);
        __half2 h0 = __floats2half2_rn(v.x, v.y);
        __half2 h1 = __floats2half2_rn(v.z, v.w);
        uint2 pack;
        pack.x = *reinterpret_cast<uint32_t*>(&h0);
        pack.y = *reinterpret_cast<uint32_t*>(&h1);
        *reinterpret_cast<uint2*>(g_xh + 4 * i) = pack;
    }
    if (i < EE) {
        int d = s_is64 ? (int)((const long long*)ei)[EE + i] : ei32[EE + i];
        atomicAdd(&g_cnt[d], 1);
    }
    if (i == 0) g_is64 = s_is64;   // for later kernels
}

// ---------------- single-pass parallel scan (49 blocks x 1024) --------------------
// Each block: cooperative sum of all counts before its chunk -> block offset,
// then 1024-wide Hillis-Steele over its own chunk.
__global__ __launch_bounds__(1024) void k_scan() {
    __shared__ int s[1024];
    const int t = threadIdx.x;
    const int b = blockIdx.x;
    const int chunk = b * 1024;

    // cooperative prefix: sum of g_cnt[0 .. chunk)
    int pre = 0;
    for (int i = t; i < chunk; i += 1024) pre += g_cnt[i];
    s[t] = pre;
    __syncthreads();
    for (int o = 512; o > 0; o >>= 1) {
        if (t < o) s[t] += s[t + o];
        __syncthreads();
    }
    const int boff = s[0];
    __syncthreads();

    // block-local inclusive scan of own chunk
    int gid = chunk + t;
    int v = (gid < NN) ? g_cnt[gid] : 0;
    s[t] = v;
    __syncthreads();
    for (int o = 1; o < 1024; o <<= 1) {
        int x = (t >= o) ? s[t - o] : 0;
        __syncthreads();
        s[t] += x;
        __syncthreads();
    }
    if (gid < NN) {
        int f = boff + s[t];
        g_offs[gid + 1] = f;
        g_cursor[gid] = f - v;
        if (gid == 0) g_offs[0] = 0;
    }
}

// scatter (R14-proven: 1 edge/thread) + re-zero counters (keeps g_cnt==0 invariant)
__global__ void k_scatter(const void* __restrict__ ei) {
    int e = blockIdx.x * blockDim.x + threadIdx.x;
    if (e < EE) {
        int s = edge_val(ei, e);
        int d = edge_val(ei, EE + e);
        int pos = atomicAdd(&g_cursor[d], 1);
        g_src[pos] = s;
    }
    if (e < NN) g_cnt[e] = 0;
}

// ---------------- fp16 gather-sum of one node row (warp-collective) ---------------
__device__ __forceinline__ float2 gather_row_h(const __half* __restrict__ feat,
                                               int node, int lane) {
    int s = g_offs[node], e = g_offs[node + 1];
    float2 a0 = make_float2(0.f, 0.f), a1 = make_float2(0.f, 0.f);
    float2 a2 = make_float2(0.f, 0.f), a3 = make_float2(0.f, 0.f);
    int i = s;
    for (; i + 4 <= e; i += 4) {
        int s0 = __ldg(&g_src[i]),     s1 = __ldg(&g_src[i + 1]);
        int s2 = __ldg(&g_src[i + 2]), s3 = __ldg(&g_src[i + 3]);
        float2 v0 = __half22float2(*reinterpret_cast<const __half2*>(feat + (size_t)s0 * 64 + 2 * lane));
        float2 v1 = __half22float2(*reinterpret_cast<const __half2*>(feat + (size_t)s1 * 64 + 2 * lane));
        float2 v2 = __half22float2(*reinterpret_cast<const __half2*>(feat + (size_t)s2 * 64 + 2 * lane));
        float2 v3 = __half22float2(*reinterpret_cast<const __half2*>(feat + (size_t)s3 * 64 + 2 * lane));
        a0.x += v0.x; a0.y += v0.y;  a1.x += v1.x; a1.y += v1.y;
        a2.x += v2.x; a2.y += v2.y;  a3.x += v3.x; a3.y += v3.y;
    }
    for (; i < e; i++) {
        int sr = __ldg(&g_src[i]);
        float2 v = __half22float2(*reinterpret_cast<const __half2*>(feat + (size_t)sr * 64 + 2 * lane));
        a0.x += v.x; a0.y += v.y;
    }
    return make_float2((a0.x + a1.x) + (a2.x + a3.x),
                       (a0.y + a1.y) + (a2.y + a3.y));
}

// ---------------- layer-1 aggregation: agg1h = segsum(xh[src]) fp16 ---------------
__global__ void k_agg1() {
    int w = (blockIdx.x * blockDim.x + threadIdx.x) >> 5;
    if (w >= NN) return;
    int lane = threadIdx.x & 31;
    float2 acc = gather_row_h(g_xh, w, lane);
    __half2 hp = __floats2half2_rn(acc.x, acc.y);
    *reinterpret_cast<uint32_t*>(g_agg1h + (size_t)w * 64 + 2 * lane) =
        *reinterpret_cast<uint32_t*>(&hp);
}

// ---------------- fp16 mma m16n8k16 ----------------
__device__ __forceinline__ void mma_f16(float4& d, const uint32_t* a, const uint32_t* b) {
    asm volatile("mma.sync.aligned.m16n8k16.row.col.f32.f16.f16.f32 "
        "{%0,%1,%2,%3}, {%4,%5,%6,%7}, {%8,%9}, {%0,%1,%2,%3};"
        : "+f"(d.x), "+f"(d.y), "+f"(d.z), "+f"(d.w)
        : "r"(a[0]), "r"(a[1]), "r"(a[2]), "r"(a[3]), "r"(b[0]), "r"(b[1]));
}

// ---------------- layer 1: fp16 GEMM + register epilogue (norm/BN/ReLU) -----------
// h = relu(bn(l2norm([agg1h|xh] @ [W1l;W1r] + b1))), h stored fp16.
__global__ __launch_bounds__(256, 3)
void k_tgemm1(const float* __restrict__ Wl, const float* __restrict__ Wr,
              const float* __restrict__ bias,
              const float* __restrict__ gam, const float* __restrict__ bet,
              const float* __restrict__ rm,  const float* __restrict__ rv) {
    constexpr int BM = 64, K = 128, NOUT = 128;
    extern __shared__ __half smh[];
    __half* Ws16 = smh;                          // [NOUT][WS_H]
    __half* As16 = smh + NOUT * WS_H;            // [BM][AS_H]
    float*  ssqp = reinterpret_cast<float*>(smh + NOUT * WS_H + BM * AS_H);  // [4][64]

    const int tid  = threadIdx.x;
    const int lane = tid & 31, wid = tid >> 5;
    const int g = lane >> 2, t = lane & 3;
    const int wm = wid >> 2, wn = wid & 3;

    // stage W transposed: Ws16[n][k] = W[k][n]
    for (int v = tid; v < (K * NOUT) / 4; v += 256) {
        int n = v & 127, k0 = (v >> 7) * 4;
        float w0, w1, w2, w3;
        if (k0 < 64) {
            w0 = Wl[k0 * NOUT + n];       w1 = Wl[(k0 + 1) * NOUT + n];
            w2 = Wl[(k0 + 2) * NOUT + n]; w3 = Wl[(k0 + 3) * NOUT + n];
        } else {
            int kk = k0 - 64;
            w0 = Wr[kk * NOUT + n];       w1 = Wr[(kk + 1) * NOUT + n];
            w2 = Wr[(kk + 2) * NOUT + n]; w3 = Wr[(kk + 3) * NOUT + n];
        }
        __half2 p0 = __floats2half2_rn(w0, w1), p1 = __floats2half2_rn(w2, w3);
        uint2 pk;
        pk.x = *reinterpret_cast<uint32_t*>(&p0);
        pk.y = *reinterpret_cast<uint32_t*>(&p1);
        *reinterpret_cast<uint2*>(Ws16 + n * WS_H + k0) = pk;
    }

    // per-lane column params for this warp's columns c = wn*32 + j*8 + 2t
    float2 bb[4], Am[4], Cm[4];
#pragma unroll
    for (int j = 0; j < 4; j++) {
        int c = wn * 32 + j * 8 + 2 * t;
        bb[j] = *reinterpret_cast<const float2*>(bias + c);
        float2 Gv = *reinterpret_cast<const float2*>(gam + c);
        float2 Rv = *reinterpret_cast<const float2*>(rv  + c);
        float2 Mv = *reinterpret_cast<const float2*>(rm  + c);
        float2 Bv = *reinterpret_cast<const float2*>(bet + c);
        float isx = rsqrtf(Rv.x + 1e-5f), isy = rsqrtf(Rv.y + 1e-5f);
        Am[j] = make_float2(Gv.x * isx, Gv.y * isy);
        Cm[j] = make_float2(Bv.x - Am[j].x * Mv.x, Bv.y - Am[j].y * Mv.y);
    }

    const int numTiles = (NN + BM - 1) / BM;
    for (int tile = blockIdx.x; tile < numTiles; tile += gridDim.x) {
        __syncthreads();   // As16 + ssqp reads of previous tile done
        const int base = tile * BM;

        for (int v = tid; v < (BM * K) / 4; v += 256) {
            int idx = v * 4, r = idx >> 7, c = idx & 127;
            int node = base + r;
            uint2 pk = make_uint2(0u, 0u);
            if (node < NN) {
                if (c < 64) pk = *reinterpret_cast<const uint2*>(g_agg1h + (size_t)node * 64 + c);
                else        pk = *reinterpret_cast<const uint2*>(g_xh + (size_t)node * 64 + (c - 64));
            }
            *reinterpret_cast<uint2*>(As16 + r * AS_H + c) = pk;
        }
        __syncthreads();

        float4 acc[2][4];
#pragma unroll
        for (int i = 0; i < 2; i++)
#pragma unroll
            for (int j = 0; j < 4; j++) acc[i][j] = make_float4(0.f, 0.f, 0.f, 0.f);

#pragma unroll
        for (int kk = 0; kk < 8; kk++) {
            const int cb = kk * 16;
            uint32_t a[2][4], b[4][2];
#pragma unroll
            for (int i = 0; i < 2; i++) {
                int r0 = wm * 32 + i * 16 + g;
                const __half* p = As16 + r0 * AS_H + cb + 2 * t;
                a[i][0] = *reinterpret_cast<const uint32_t*>(p);
                a[i][1] = *reinterpret_cast<const uint32_t*>(p + 8 * AS_H);
                a[i][2] = *reinterpret_cast<const uint32_t*>(p + 8);
                a[i][3] = *reinterpret_cast<const uint32_t*>(p + 8 * AS_H + 8);
            }
#pragma unroll
            for (int j = 0; j < 4; j++) {
                int n = wn * 32 + j * 8 + g;
                const __half* p = Ws16 + n * WS_H + cb + 2 * t;
                b[j][0] = *reinterpret_cast<const uint32_t*>(p);
                b[j][1] = *reinterpret_cast<const uint32_t*>(p + 8);
            }
#pragma unroll
            for (int i = 0; i < 2; i++)
#pragma unroll
                for (int j = 0; j < 4; j++) mma_f16(acc[i][j], a[i], b[j]);
        }

        // bias + per-row partial sum of squares, quad-reduce over t
        float p0[2], p1[2];
#pragma unroll
        for (int i = 0; i < 2; i++) {
            p0[i] = 0.f; p1[i] = 0.f;
#pragma unroll
            for (int j = 0; j < 4; j++) {
                acc[i][j].x += bb[j].x; acc[i][j].y += bb[j].y;
                acc[i][j].z += bb[j].x; acc[i][j].w += bb[j].y;
                p0[i] += acc[i][j].x * acc[i][j].x + acc[i][j].y * acc[i][j].y;
                p1[i] += acc[i][j].z * acc[i][j].z + acc[i][j].w * acc[i][j].w;
            }
            p0[i] += __shfl_xor_sync(0xffffffffu, p0[i], 1);
            p0[i] += __shfl_xor_sync(0xffffffffu, p0[i], 2);
            p1[i] += __shfl_xor_sync(0xffffffffu, p1[i], 1);
            p1[i] += __shfl_xor_sync(0xffffffffu, p1[i], 2);
        }
        if (t == 0) {
#pragma unroll
            for (int i = 0; i < 2; i++) {
                int r = wm * 32 + i * 16 + g;
                ssqp[wn * 64 + r]     = p0[i];
                ssqp[wn * 64 + r + 8] = p1[i];
            }
        }
        __syncthreads();

        // total ssq, normalize, BN(+ReLU), store fp16 h from registers
#pragma unroll
        for (int i = 0; i < 2; i++) {
            int r = wm * 32 + i * 16 + g;
            float ss0 = ssqp[r] + ssqp[64 + r] + ssqp[128 + r] + ssqp[192 + r];
            float ss1 = ssqp[r + 8] + ssqp[64 + r + 8] + ssqp[128 + r + 8] + ssqp[192 + r + 8];
            float sc0 = 1.0f / fmaxf(sqrtf(ss0), 1e-12f);
            float sc1 = 1.0f / fmaxf(sqrtf(ss1), 1e-12f);
            int n0 = base + r, n1 = n0 + 8;
#pragma unroll
            for (int j = 0; j < 4; j++) {
                int c = wn * 32 + j * 8 + 2 * t;
                if (n0 < NN) {
                    float ox = fmaxf(Am[j].x * (acc[i][j].x * sc0) + Cm[j].x, 0.f);
                    float oy = fmaxf(Am[j].y * (acc[i][j].y * sc0) + Cm[j].y, 0.f);
                    __half2 hp = __floats2half2_rn(ox, oy);
                    *reinterpret_cast<uint32_t*>(g_h + (size_t)n0 * NOUT + c) =
                        *reinterpret_cast<uint32_t*>(&hp);
                }
                if (n1 < NN) {
                    float oz = fmaxf(Am[j].x * (acc[i][j].z * sc1) + Cm[j].x, 0.f);
                    float ow = fmaxf(Am[j].y * (acc[i][j].w * sc1) + Cm[j].y, 0.f);
                    __half2 hp = __floats2half2_rn(oz, ow);
                    *reinterpret_cast<uint32_t*>(g_h + (size_t)n1 * NOUT + c) =
                        *reinterpret_cast<uint32_t*>(&hp);
                }
            }
        }
    }
}

// ---------------- layer 2 projection: y(fp16)=h@W2l ; z(fp32)=h@W2r+b2 ------------
__global__ __launch_bounds__(256)
void k_tgemm2(const float* __restrict__ Wl, const float* __restrict__ Wr,
              const float* __restrict__ bias) {
    constexpr int BM = 64, K = 128, NOUT = 128;
    extern __shared__ __half smh[];
    __half* Ws16 = smh;                    // [NOUT][WS_H]
    __half* As16 = smh + NOUT * WS_H;      // [BM][AS_H]

    const int tid  = threadIdx.x;
    const int lane = tid & 31, wid = tid >> 5;
    const int g = lane >> 2, t = lane & 3;
    const int wm = wid >> 2, wn = wid & 3;

    for (int v = tid; v < (K * NOUT) / 4; v += 256) {
        int n = v & 127, k0 = (v >> 7) * 4;
        float w0, w1, w2, w3;
        if (n < 64) {
            w0 = Wl[k0 * 64 + n];       w1 = Wl[(k0 + 1) * 64 + n];
            w2 = Wl[(k0 + 2) * 64 + n]; w3 = Wl[(k0 + 3) * 64 + n];
        } else {
            int nn = n - 64;
            w0 = Wr[k0 * 64 + nn];       w1 = Wr[(k0 + 1) * 64 + nn];
            w2 = Wr[(k0 + 2) * 64 + nn]; w3 = Wr[(k0 + 3) * 64 + nn];
        }
        __half2 p0 = __floats2half2_rn(w0, w1), p1 = __floats2half2_rn(w2, w3);
        uint2 pk;
        pk.x = *reinterpret_cast<uint32_t*>(&p0);
        pk.y = *reinterpret_cast<uint32_t*>(&p1);
        *reinterpret_cast<uint2*>(Ws16 + n * WS_H + k0) = pk;
    }

    float2 bz[4];
#pragma unroll
    for (int j = 0; j < 4; j++) {
        int c = wn * 32 + j * 8 + 2 * t;
        if (c >= 64) bz[j] = *reinterpret_cast<const float2*>(bias + (c - 64));
        else         bz[j] = make_float2(0.f, 0.f);
    }

    const int numTiles = (NN + BM - 1) / BM;
    for (int tile = blockIdx.x; tile < numTiles; tile += gridDim.x) {
        __syncthreads();
        const int base = tile * BM;

        for (int v = tid; v < (BM * K) / 4; v += 256) {
            int idx = v * 4, r = idx >> 7, c = idx & 127;
            int node = base + r;
            uint2 pk = make_uint2(0u, 0u);
            if (node < NN)
                pk = *reinterpret_cast<const uint2*>(g_h + (size_t)node * 128 + c);
            *reinterpret_cast<uint2*>(As16 + r * AS_H + c) = pk;
        }
        __syncthreads();

        float4 acc[2][4];
#pragma unroll
        for (int i = 0; i < 2; i++)
#pragma unroll
            for (int j = 0; j < 4; j++) acc[i][j] = make_float4(0.f, 0.f, 0.f, 0.f);

#pragma unroll
        for (int kk = 0; kk < 8; kk++) {
            const int cb = kk * 16;
            uint32_t a[2][4], b[4][2];
#pragma unroll
            for (int i = 0; i < 2; i++) {
                int r0 = wm * 32 + i * 16 + g;
                const __half* p = As16 + r0 * AS_H + cb + 2 * t;
                a[i][0] = *reinterpret_cast<const uint32_t*>(p);
                a[i][1] = *reinterpret_cast<const uint32_t*>(p + 8 * AS_H);
                a[i][2] = *reinterpret_cast<const uint32_t*>(p + 8);
                a[i][3] = *reinterpret_cast<const uint32_t*>(p + 8 * AS_H + 8);
            }
#pragma unroll
            for (int j = 0; j < 4; j++) {
                int n = wn * 32 + j * 8 + g;
                const __half* p = Ws16 + n * WS_H + cb + 2 * t;
                b[j][0] = *reinterpret_cast<const uint32_t*>(p);
                b[j][1] = *reinterpret_cast<const uint32_t*>(p + 8);
            }
#pragma unroll
            for (int i = 0; i < 2; i++)
#pragma unroll
                for (int j = 0; j < 4; j++) mma_f16(acc[i][j], a[i], b[j]);
        }

#pragma unroll
        for (int i = 0; i < 2; i++) {
            int r0 = base + wm * 32 + i * 16 + g;
            int r1 = r0 + 8;
#pragma unroll
            for (int j = 0; j < 4; j++) {
                int c = wn * 32 + j * 8 + 2 * t;
                float4 v = acc[i][j];
                if (c < 64) {
                    if (r0 < NN) {
                        __half2 hp = __floats2half2_rn(v.x, v.y);
                        *reinterpret_cast<uint32_t*>(g_yh + (size_t)r0 * 64 + c) =
                            *reinterpret_cast<uint32_t*>(&hp);
                    }
                    if (r1 < NN) {
                        __half2 hp = __floats2half2_rn(v.z, v.w);
                        *reinterpret_cast<uint32_t*>(g_yh + (size_t)r1 * 64 + c) =
                            *reinterpret_cast<uint32_t*>(&hp);
                    }
                } else {
                    int cz = c - 64;
                    if (r0 < NN)
                        *reinterpret_cast<float2*>(g_z + (size_t)r0 * 64 + cz) =
                            make_float2(v.x + bz[j].x, v.y + bz[j].y);
                    if (r1 < NN)
                        *reinterpret_cast<float2*>(g_z + (size_t)r1 * 64 + cz) =
                            make_float2(v.z + bz[j].x, v.w + bz[j].y);
                }
            }
        }
    }
}

// ---------------- layer-2 final: gather y(fp16), add z, L2norm, BN -> out ---------
__global__ void k_final(const float* __restrict__ gam, const float* __restrict__ bet,
                        const float* __restrict__ rm,  const float* __restrict__ rv,
                        float* __restrict__ out) {
    int w = (blockIdx.x * blockDim.x + threadIdx.x) >> 5;
    if (w >= NN) return;
    int lane = threadIdx.x & 31;

    float2 v = gather_row_h(g_yh, w, lane);
    float2 z = *reinterpret_cast<const float2*>(g_z + (size_t)w * 64 + 2 * lane);
    v.x += z.x; v.y += z.y;

    float ss = v.x * v.x + v.y * v.y;
#pragma unroll
    for (int o = 16; o > 0; o >>= 1) ss += __shfl_xor_sync(0xffffffffu, ss, o);
    float scale = 1.0f / fmaxf(sqrtf(ss), 1e-12f);

    float2 G  = *reinterpret_cast<const float2*>(gam + 2 * lane);
    float2 B  = *reinterpret_cast<const float2*>(bet + 2 * lane);
    float2 RM = *reinterpret_cast<const float2*>(rm  + 2 * lane);
    float2 RV = *reinterpret_cast<const float2*>(rv  + 2 * lane);
    float2 o;
    o.x = G.x * (v.x * scale - RM.x) * rsqrtf(RV.x + 1e-5f) + B.x;
    o.y = G.y * (v.y * scale - RM.y) * rsqrtf(RV.y + 1e-5f) + B.y;
    *reinterpret_cast<float2*>(out + (size_t)w * 64 + 2 * lane) = o;
}

// ---------------- launch ----------------
extern "C" void kernel_launch(void* const* d_in, const int* in_sizes, int n_in,
                              void* d_out, int out_size) {
    const float* x    = (const float*)d_in[0];
    const void*  ei   = d_in[1];
    const float* W1l  = (const float*)d_in[2];
    const float* b1   = (const float*)d_in[3];
    const float* W1r  = (const float*)d_in[4];
    const float* gam1 = (const float*)d_in[5];
    const float* bet1 = (const float*)d_in[6];
    const float* rm1  = (const float*)d_in[7];
    const float* rv1  = (const float*)d_in[8];
    const float* W2l  = (const float*)d_in[9];
    const float* b2   = (const float*)d_in[10];
    const float* W2r  = (const float*)d_in[11];
    const float* gam2 = (const float*)d_in[12];
    const float* bet2 = (const float*)d_in[13];
    const float* rm2  = (const float*)d_in[14];
    const float* rv2  = (const float*)d_in[15];
    float* out = (float*)d_out;

    constexpr int SMEM1 = (128 * WS_H + 64 * AS_H) * 2 + 4 * 64 * 4;  // 53,248 B
    constexpr int SMEM2 = (128 * WS_H + 64 * AS_H) * 2;               // 52,224 B
    cudaFuncSetAttribute(k_tgemm1, cudaFuncAttributeMaxDynamicSharedMemorySize, SMEM1);
    cudaFuncSetAttribute(k_tgemm2, cudaFuncAttributeMaxDynamicSharedMemorySize, SMEM2);

    const int NB = (NN + 1023) / 1024;
    const int EB = (EE + 255) / 256;
    const int WARP_BLOCKS = (NN * 32 + 255) / 256;

    // fused front-end: (convert + detect + hist) -> merged parallel scan -> (scatter + re-zero)
    k_init<<<EB, 256>>>(x, ei);
    k_scan<<<NB, 1024>>>();
    k_scatter<<<EB, 256>>>(ei);

    // layer 1: fp16 gather -> fp16 tensor GEMM + register epilogue (h fp16)
    k_agg1<<<WARP_BLOCKS, 256>>>();
    k_tgemm1<<<444, 256, SMEM1>>>(W1l, W1r, b1, gam1, bet1, rm1, rv1);

    // layer 2: fp16 projection GEMM (y fp16, z fp32, direct epilogue) -> final
    k_tgemm2<<<592, 256, SMEM2>>>(W2l, W2r, b2);
    k_final<<<WARP_BLOCKS, 256>>>(gam2, bet2, rm2, rv2, out);
}